// round 2
// baseline (speedup 1.0000x reference)
#include <cuda_runtime.h>
#include <math.h>

#define NB 8            // batch
#define CIN 16
#define CA 8            // channels after pre-conv
#define TT 160
#define HW 2304         // 48*48
#define THW (TT*HW)     // 368640
#define DD 160          // D = T/S
#define NN (CA*HW)      // 18432
#define BSTRIDE (DD*NN) // 2949120 per batch
#define FEPS 1e-6f
#define NITER 4

// Scratch (allocation-free rule: __device__ globals)
__device__ float g_h[NB * BSTRIDE];           // x3 = relu(pre-conv), 94.4 MB
__device__ float g_bases[NB * DD];
__device__ float g_coef[NB * NN];
__device__ float g_numb[NITER * NB * DD];     // bases-update numerators (atomic accum)
__device__ float g_ctc [NITER * NB];          // sum coef^2 per (iter, b)

// ---------------------------------------------------------------------------
// Kernel 1: pre 1x1x1 conv (16->8) + ReLU, float4 vectorized. Also folds in
// all tiny initializations (coef=1 from size-1 softmax, bases=1/sqrt(D),
// zeroed atomic accumulators) — grid is large enough to cover them.
// ---------------------------------------------------------------------------
__global__ void k_preconv(const float* __restrict__ x,
                          const float* __restrict__ Wpre) {
    __shared__ float sW[CA * CIN];
    int tid = threadIdx.x;
    if (tid < CA * CIN) sW[tid] = Wpre[tid];
    __syncthreads();

    long gid = (long)blockIdx.x * blockDim.x + tid;   // over NB * THW/4
    if (gid < NB * NN) g_coef[gid] = 1.0f;            // softmax over size-1 axis
    if (gid < NB * DD) g_bases[gid] = 1.0f / sqrtf((float)DD);
    if (gid < NITER * NB * DD) g_numb[gid] = 0.0f;
    if (gid < NITER * NB)      g_ctc[gid]  = 0.0f;

    const long NV = (long)NB * (THW / 4);
    if (gid >= NV) return;
    int b  = (int)(gid / (THW / 4));
    int i4 = (int)(gid % (THW / 4));

    const float4* xb = (const float4*)(x + (size_t)b * CIN * THW);
    float4 acc[CA];
#pragma unroll
    for (int o = 0; o < CA; o++) acc[o] = make_float4(0.f, 0.f, 0.f, 0.f);

#pragma unroll
    for (int c = 0; c < CIN; c++) {
        float4 xv = xb[(size_t)c * (THW / 4) + i4];
#pragma unroll
        for (int o = 0; o < CA; o++) {
            float w = sW[o * CIN + c];
            acc[o].x = fmaf(w, xv.x, acc[o].x);
            acc[o].y = fmaf(w, xv.y, acc[o].y);
            acc[o].z = fmaf(w, xv.z, acc[o].z);
            acc[o].w = fmaf(w, xv.w, acc[o].w);
        }
    }
    float4* hb = (float4*)g_h + (size_t)b * CA * (THW / 4) + i4;
#pragma unroll
    for (int o = 0; o < CA; o++) {
        float4 v = acc[o];
        v.x = fmaxf(v.x, 0.f); v.y = fmaxf(v.y, 0.f);
        v.z = fmaxf(v.z, 0.f); v.w = fmaxf(v.w, 0.f);
        hb[(size_t)o * (THW / 4)] = v;
    }
}

// ---------------------------------------------------------------------------
// Kernel 2: fused coef multiplicative update + bases-update partials.
//   Pass 1 (per thread, one n): num[n] = sum_d x3[d,n]*bases[d]; btb = sum b^2
//           coef_new = coef * num / (coef*btb + eps)
//   Pass 2 (doPartials): re-walk the same x3 column (L1/L2 hot) and reduce
//           numb[d] += sum_{n in block} x3[d,n]*coef_new[n]  (warp shuffles,
//           per-warp smem partials, one atomicAdd per (block,d)).
//           ctc[b]  += sum coef_new^2.
// grid (NN/256, NB), 256 threads.
// ---------------------------------------------------------------------------
__global__ void k_step(int iter, int doPartials) {
    int b = blockIdx.y;
    int n = blockIdx.x * 256 + threadIdx.x;
    int lane = threadIdx.x & 31, warp = threadIdx.x >> 5;

    __shared__ float sb[DD];
    __shared__ float spart[DD * 8];
    __shared__ float sctc[8];
    if (threadIdx.x < DD) sb[threadIdx.x] = g_bases[b * DD + threadIdx.x];
    __syncthreads();

    const float* xb = g_h + (size_t)b * BSTRIDE + n;
    float acc = 0.f, btb = 0.f;
#pragma unroll 8
    for (int d = 0; d < DD; d++) {
        float bv = sb[d];
        acc = fmaf(xb[(size_t)d * NN], bv, acc);
        btb = fmaf(bv, bv, btb);
    }
    float c = g_coef[b * NN + n];
    float cnew = c * acc / (c * btb + FEPS);
    g_coef[b * NN + n] = cnew;

    if (doPartials) {
        // ctc partial (block reduce)
        float c2 = cnew * cnew;
#pragma unroll
        for (int o = 16; o; o >>= 1) c2 += __shfl_xor_sync(0xFFFFFFFFu, c2, o);
        if (lane == 0) sctc[warp] = c2;

        // numb partials: second pass over the (hot) x3 column
#pragma unroll 4
        for (int d = 0; d < DD; d++) {
            float v = xb[(size_t)d * NN] * cnew;
#pragma unroll
            for (int o = 16; o; o >>= 1) v += __shfl_xor_sync(0xFFFFFFFFu, v, o);
            if (lane == 0) spart[d * 8 + warp] = v;
        }
        __syncthreads();

        if (threadIdx.x < DD) {
            float s = 0.f;
#pragma unroll
            for (int w = 0; w < 8; w++) s += spart[threadIdx.x * 8 + w];
            atomicAdd(&g_numb[(iter * NB + b) * DD + threadIdx.x], s);
        }
        if (threadIdx.x == 0) {
            float s = 0.f;
#pragma unroll
            for (int w = 0; w < 8; w++) s += sctc[w];
            atomicAdd(&g_ctc[iter * NB + b], s);
        }
    }
}

// ---------------------------------------------------------------------------
// Kernel 3: bases finalize (tiny).  bases[d] *= numb[d] / (bases[d]*ctc + eps)
// ---------------------------------------------------------------------------
__global__ void k_bfin(int iter) {
    int b = blockIdx.x, d = threadIdx.x;  // <<<NB, DD>>>
    float bo  = g_bases[b * DD + d];
    float ctc = g_ctc[iter * NB + b];
    float nm  = g_numb[(iter * NB + b) * DD + d];
    g_bases[b * DD + d] = bo * nm / (bo * ctc + FEPS);
}

// ---------------------------------------------------------------------------
// Kernel 4: epilogue. recon is rank-1 and nonneg, so both post convs collapse:
//   y[b,co,t,hw] = u[b,t,co] * coef[b, (t%8)*HW + hw]
// with u = Wpost2 @ relu(Wpost1 @ bvec), bvec[ca]=bases[b, ca*20 + t/8].
// grid (TT, NB), 256 threads; block handles one (b,t): 16*2304 output floats.
// ---------------------------------------------------------------------------
__global__ void k_out(const float* __restrict__ Wp1,
                      const float* __restrict__ Wp2,
                      float* __restrict__ y) {
    int b = blockIdx.y, t = blockIdx.x;
    __shared__ float su[16];
    __shared__ float sc[HW];

    const float4* cs = (const float4*)(g_coef + (size_t)b * NN + (t & 7) * HW);
    for (int i = threadIdx.x; i < HW / 4; i += 256)
        ((float4*)sc)[i] = cs[i];

    if (threadIdx.x == 0) {
        float bvec[8], tmp[8];
        int td = t >> 3;
#pragma unroll
        for (int ca = 0; ca < 8; ca++) bvec[ca] = g_bases[b * DD + ca * 20 + td];
#pragma unroll
        for (int o = 0; o < 8; o++) {
            float a = 0.f;
#pragma unroll
            for (int c = 0; c < 8; c++) a = fmaf(Wp1[o * 8 + c], bvec[c], a);
            tmp[o] = fmaxf(a, 0.f);
        }
#pragma unroll
        for (int o = 0; o < 16; o++) {
            float a = 0.f;
#pragma unroll
            for (int c = 0; c < 8; c++) a = fmaf(Wp2[o * 8 + c], tmp[c], a);
            su[o] = a;
        }
    }
    __syncthreads();

    float* yb = y + ((size_t)b * 16) * THW + (size_t)t * HW;
#pragma unroll 4
    for (int co = 0; co < 16; co++) {
        float u = su[co];
        float4* yo = (float4*)(yb + (size_t)co * THW);
        for (int i = threadIdx.x; i < HW / 4; i += 256) {
            float4 cv = ((float4*)sc)[i];
            yo[i] = make_float4(u * cv.x, u * cv.y, u * cv.z, u * cv.w);
        }
    }
}

// ---------------------------------------------------------------------------
extern "C" void kernel_launch(void* const* d_in, const int* in_sizes, int n_in,
                              void* d_out, int out_size) {
    const float* x    = (const float*)d_in[0];  // [8,16,160,48,48]
    const float* Wpre = (const float*)d_in[1];  // [8,16]
    const float* Wp1  = (const float*)d_in[2];  // [8,8]
    const float* Wp2  = (const float*)d_in[3];  // [16,8]
    float* y = (float*)d_out;                   // [8,16,160,48,48]

    // pre-conv + all initializations
    k_preconv<<<(NB * (THW / 4) + 255) / 256, 256>>>(x, Wpre);

    // 4 local steps: fused coef update + bases partials, then tiny finalize
    for (int it = 0; it < NITER; it++) {
        k_step<<<dim3(NN / 256, NB), 256>>>(it, 1);
        k_bfin<<<NB, DD>>>(it);
    }
    // final (differentiable) coef update — no partials
    k_step<<<dim3(NN / 256, NB), 256>>>(0, 0);

    // fused rank-1 reconstruction + both post convs
    k_out<<<dim3(TT, NB), 256>>>(Wp1, Wp2, y);
}

// round 8
// speedup vs baseline: 1.1983x; 1.1983x over previous
#include <cuda_runtime.h>
#include <cuda_fp16.h>
#include <math.h>

#define NB 8            // batch
#define CIN 16
#define CA 8            // channels after pre-conv
#define TT 160
#define HW 2304         // 48*48
#define THW (TT*HW)     // 368640
#define DD 160          // D = T/S
#define NN (CA*HW)      // 18432
#define NN2 (NN/2)      // 9216 half2 per (b,d) row
#define BSTRIDE (DD*NN) // 2949120 per batch
#define FEPS 1e-6f
#define NITER 4
#define BINIT 0.07905694150420949f   // 1/sqrt(160)
#define SX_BYTES (DD * 128 * sizeof(__half2))   // 81920 B dynamic smem

// Scratch (allocation-free rule: __device__ globals)
__device__ __half g_h16[NB * BSTRIDE];        // x3 = relu(pre-conv), fp16, 47.2 MB
__device__ float  g_coef[NB * NN];
__device__ float  g_numb[NITER * NB * DD];    // bases-update numerators (atomic accum)
__device__ float  g_ctc [NITER * NB];         // sum coef^2 per (iter, b)

// Recompute bases[d] after `iters` completed multiplicative updates from the
// per-iteration accumulators. Chain is tiny (<= 4 steps).
__device__ __forceinline__ float bases_chain(int b, int d, int iters) {
    float bv = BINIT;
    for (int it = 0; it < iters; it++) {
        float nm  = g_numb[(it * NB + b) * DD + d];
        float ctc = g_ctc[it * NB + b];
        bv = bv * nm / (bv * ctc + FEPS);
    }
    return bv;
}

// ---------------------------------------------------------------------------
// Kernel 1: pre 1x1x1 conv (16->8) + ReLU -> fp16. Folds in the tiny inits
// (coef=1 from size-1 softmax; zeroed accumulators).
// ---------------------------------------------------------------------------
__global__ void k_preconv(const float* __restrict__ x,
                          const float* __restrict__ Wpre) {
    __shared__ float sW[CA * CIN];
    int tid = threadIdx.x;
    if (tid < CA * CIN) sW[tid] = Wpre[tid];
    __syncthreads();

    long gid = (long)blockIdx.x * blockDim.x + tid;   // over NB * THW/4
    if (gid < NB * NN) g_coef[gid] = 1.0f;            // softmax over size-1 axis
    if (gid < NITER * NB * DD) g_numb[gid] = 0.0f;
    if (gid < NITER * NB)      g_ctc[gid]  = 0.0f;

    const long NV = (long)NB * (THW / 4);
    if (gid >= NV) return;
    int b  = (int)(gid / (THW / 4));
    int i4 = (int)(gid % (THW / 4));

    const float4* xb = (const float4*)(x + (size_t)b * CIN * THW);
    float4 acc[CA];
#pragma unroll
    for (int o = 0; o < CA; o++) acc[o] = make_float4(0.f, 0.f, 0.f, 0.f);

#pragma unroll
    for (int c = 0; c < CIN; c++) {
        float4 xv = xb[(size_t)c * (THW / 4) + i4];
#pragma unroll
        for (int o = 0; o < CA; o++) {
            float w = sW[o * CIN + c];
            acc[o].x = fmaf(w, xv.x, acc[o].x);
            acc[o].y = fmaf(w, xv.y, acc[o].y);
            acc[o].z = fmaf(w, xv.z, acc[o].z);
            acc[o].w = fmaf(w, xv.w, acc[o].w);
        }
    }
#pragma unroll
    for (int o = 0; o < CA; o++) {
        float4 v = acc[o];
        __half2 lo = __floats2half2_rn(fmaxf(v.x, 0.f), fmaxf(v.y, 0.f));
        __half2 hi = __floats2half2_rn(fmaxf(v.z, 0.f), fmaxf(v.w, 0.f));
        __half* p = g_h16 + (size_t)b * CA * THW + (size_t)o * THW + 4 * (size_t)i4;
        uint2 pk;
        pk.x = *(unsigned*)&lo; pk.y = *(unsigned*)&hi;
        *(uint2*)p = pk;
    }
}

// ---------------------------------------------------------------------------
// Kernel 2: fused NMF step (half2 data, fp32 math), 128 threads, grid (72,NB).
//   Pass 1 (thread-per-2n): num[n] = sum_d x3[d,n]*bases[d], while staging the
//     raw half2 column slice into DYNAMIC smem (80 KB); coef_new -> smem+gmem.
//   Pass 2 (doPartials): warp w owns d in [40w, 40w+40); reduces rows FROM
//     SMEM (x3 read globally exactly once per iteration):
//       numb[d] += sum_{n in block} x3[d,n]*coef_new[n]   (1 atomic per d)
//       ctc     += sum coef_new^2
//   Final step launches with 0 dynamic smem (sx untouched) for occupancy.
// ---------------------------------------------------------------------------
__global__ void k_step(int iter, int doPartials) {
    extern __shared__ __half2 sx[];    // DD*128 half2 = 80 KB when partials
    const int b = blockIdx.y;
    const int tid = threadIdx.x;
    const int lane = tid & 31, warp = tid >> 5;
    const int n2 = blockIdx.x * 128 + tid;

    __shared__ float  sb[DD];
    __shared__ float2 scnew[128];
    __shared__ float  sctc[4];

    for (int d = tid; d < DD; d += 128) sb[d] = bases_chain(b, d, iter);
    __syncthreads();

    const __half2* xb = (const __half2*)g_h16 + (size_t)b * (BSTRIDE / 2) + n2;

    // Pass 1: 4 independent accumulator chains for ILP; stage raw half2 to smem
    float ax0 = 0.f, ay0 = 0.f, ax1 = 0.f, ay1 = 0.f, btb = 0.f;
    if (doPartials) {
#pragma unroll 8
        for (int d = 0; d < DD; d += 2) {
            float bv0 = sb[d], bv1 = sb[d + 1];
            __half2 h0 = xb[(size_t)d * NN2];
            __half2 h1 = xb[(size_t)(d + 1) * NN2];
            sx[d * 128 + tid]       = h0;
            sx[(d + 1) * 128 + tid] = h1;
            float2 x0 = __half22float2(h0);
            float2 x1 = __half22float2(h1);
            ax0 = fmaf(x0.x, bv0, ax0); ay0 = fmaf(x0.y, bv0, ay0);
            ax1 = fmaf(x1.x, bv1, ax1); ay1 = fmaf(x1.y, bv1, ay1);
            btb = fmaf(bv0, bv0, btb);  btb = fmaf(bv1, bv1, btb);
        }
    } else {
#pragma unroll 8
        for (int d = 0; d < DD; d += 2) {
            float bv0 = sb[d], bv1 = sb[d + 1];
            float2 x0 = __half22float2(xb[(size_t)d * NN2]);
            float2 x1 = __half22float2(xb[(size_t)(d + 1) * NN2]);
            ax0 = fmaf(x0.x, bv0, ax0); ay0 = fmaf(x0.y, bv0, ay0);
            ax1 = fmaf(x1.x, bv1, ax1); ay1 = fmaf(x1.y, bv1, ay1);
            btb = fmaf(bv0, bv0, btb);  btb = fmaf(bv1, bv1, btb);
        }
    }
    float2 c = ((const float2*)g_coef)[(size_t)b * NN2 + n2];
    float cnx = c.x * (ax0 + ax1) / (c.x * btb + FEPS);
    float cny = c.y * (ay0 + ay1) / (c.y * btb + FEPS);
    ((float2*)g_coef)[(size_t)b * NN2 + n2] = make_float2(cnx, cny);

    if (doPartials) {
        // ctc partial
        float c2 = cnx * cnx + cny * cny;
#pragma unroll
        for (int o = 16; o; o >>= 1) c2 += __shfl_xor_sync(0xFFFFFFFFu, c2, o);
        if (lane == 0) sctc[warp] = c2;

        scnew[tid] = make_float2(cnx, cny);
        __syncthreads();

        // numb: warp-per-row-slice, rows served entirely from smem
        const int dbase = warp * 40;
        float* nb = &g_numb[(iter * NB + b) * DD];
#pragma unroll 2
        for (int dd = 0; dd < 40; dd += 4) {
            float a0 = 0.f, a1 = 0.f, a2 = 0.f, a3 = 0.f;
#pragma unroll
            for (int i = 0; i < 4; i++) {
                int col = lane + i * 32;
                float2 cv = scnew[col];
                float2 v0 = __half22float2(sx[(dbase + dd + 0) * 128 + col]);
                float2 v1 = __half22float2(sx[(dbase + dd + 1) * 128 + col]);
                float2 v2 = __half22float2(sx[(dbase + dd + 2) * 128 + col]);
                float2 v3 = __half22float2(sx[(dbase + dd + 3) * 128 + col]);
                a0 = fmaf(v0.x, cv.x, a0); a0 = fmaf(v0.y, cv.y, a0);
                a1 = fmaf(v1.x, cv.x, a1); a1 = fmaf(v1.y, cv.y, a1);
                a2 = fmaf(v2.x, cv.x, a2); a2 = fmaf(v2.y, cv.y, a2);
                a3 = fmaf(v3.x, cv.x, a3); a3 = fmaf(v3.y, cv.y, a3);
            }
#pragma unroll
            for (int o = 16; o; o >>= 1) {
                a0 += __shfl_xor_sync(0xFFFFFFFFu, a0, o);
                a1 += __shfl_xor_sync(0xFFFFFFFFu, a1, o);
                a2 += __shfl_xor_sync(0xFFFFFFFFu, a2, o);
                a3 += __shfl_xor_sync(0xFFFFFFFFu, a3, o);
            }
            if (lane == 0) {
                atomicAdd(nb + dbase + dd + 0, a0);
                atomicAdd(nb + dbase + dd + 1, a1);
                atomicAdd(nb + dbase + dd + 2, a2);
                atomicAdd(nb + dbase + dd + 3, a3);
            }
        }
        if (tid == 0)
            atomicAdd(&g_ctc[iter * NB + b], sctc[0] + sctc[1] + sctc[2] + sctc[3]);
    }
}

// ---------------------------------------------------------------------------
// Kernel 3: epilogue. recon is rank-1 and nonneg -> both post convs collapse:
//   y[b,co,t,hw] = u[b,t,co] * coef[b, (t%8)*HW + hw]
// u = Wpost2 @ relu(Wpost1 @ bvec), bvec[ca] = bases[ca*20 + t/8] (recomputed
// from the accumulator chain). grid (TT, NB), 256 threads.
// ---------------------------------------------------------------------------
__global__ void k_out(const float* __restrict__ Wp1,
                      const float* __restrict__ Wp2,
                      float* __restrict__ y) {
    int b = blockIdx.y, t = blockIdx.x;
    int tid = threadIdx.x;
    __shared__ float sbv[8], stmp[8], su[16];
    __shared__ float sc[HW];

    const float4* cs = (const float4*)(g_coef + (size_t)b * NN + (t & 7) * HW);
    for (int i = tid; i < HW / 4; i += 256)
        ((float4*)sc)[i] = cs[i];

    if (tid < 8) sbv[tid] = bases_chain(b, tid * 20 + (t >> 3), NITER);
    __syncthreads();
    if (tid < 8) {
        float a = 0.f;
#pragma unroll
        for (int cc = 0; cc < 8; cc++) a = fmaf(Wp1[tid * 8 + cc], sbv[cc], a);
        stmp[tid] = fmaxf(a, 0.f);
    }
    __syncthreads();
    if (tid < 16) {
        float a = 0.f;
#pragma unroll
        for (int cc = 0; cc < 8; cc++) a = fmaf(Wp2[tid * 8 + cc], stmp[cc], a);
        su[tid] = a;
    }
    __syncthreads();

    float* yb = y + ((size_t)b * 16) * THW + (size_t)t * HW;
#pragma unroll 4
    for (int co = 0; co < 16; co++) {
        float u = su[co];
        float4* yo = (float4*)(yb + (size_t)co * THW);
        for (int i = tid; i < HW / 4; i += 256) {
            float4 cv = ((float4*)sc)[i];
            yo[i] = make_float4(u * cv.x, u * cv.y, u * cv.z, u * cv.w);
        }
    }
}

// ---------------------------------------------------------------------------
extern "C" void kernel_launch(void* const* d_in, const int* in_sizes, int n_in,
                              void* d_out, int out_size) {
    const float* x    = (const float*)d_in[0];  // [8,16,160,48,48]
    const float* Wpre = (const float*)d_in[1];  // [8,16]
    const float* Wp1  = (const float*)d_in[2];  // [8,8]
    const float* Wp2  = (const float*)d_in[3];  // [16,8]
    float* y = (float*)d_out;                   // [8,16,160,48,48]

    // Allow >48KB dynamic smem for the staging buffer (idempotent, non-stream
    // API — legal under graph capture, no allocation involved).
    cudaFuncSetAttribute(k_step, cudaFuncAttributeMaxDynamicSharedMemorySize,
                         (int)SX_BYTES);

    // pre-conv (fp16 out) + all initializations
    k_preconv<<<(NB * (THW / 4) + 255) / 256, 256>>>(x, Wpre);

    // 4 fused local steps (coef update + bases partials); bases finalize is
    // recomputed in-block next launch from g_numb/g_ctc — no tiny kernels.
    for (int it = 0; it < NITER; it++)
        k_step<<<dim3(NN2 / 128, NB), 128, SX_BYTES>>>(it, 1);

    // final (differentiable) coef update — no partials, no staging buffer
    k_step<<<dim3(NN2 / 128, NB), 128, 0>>>(NITER, 0);

    // fused rank-1 reconstruction + both post convs
    k_out<<<dim3(TT, NB), 256>>>(Wp1, Wp2, y);
}